// round 6
// baseline (speedup 1.0000x reference)
#include <cuda_runtime.h>

#define NB 16
#define NC 3
#define IH 720
#define IW 1280
#define OUT 255
#define PER_B (NC*IH*IW)          /* 2764800 floats per batch image */
#define PER_B4 (PER_B/4)          /* 691200 float4 per batch image */
#define RBLK 74                   /* reduction blocks per batch */

__device__ float d_partial[NB * RBLK];
__device__ float d_winv[NB * OUT * OUT];   /* per-(b,oy,ox) invalid weight, channel-indep */
__device__ int   d_rowflag[NB * OUT];      /* 1 if row has any OOB corner */

// ---------------------------------------------------------------------------
// Kernel A (high-priority stream): per-batch partial sums.
// ---------------------------------------------------------------------------
__global__ void reduce_kernel(const float* __restrict__ im) {
    const int b   = blockIdx.y;
    const int blk = blockIdx.x;
    const float4* __restrict__ p = (const float4*)(im + (size_t)b * PER_B);

    const int stride = RBLK * 256;            /* 18944 */
    int i = blk * 256 + threadIdx.x;

    float a0 = 0.f, a1 = 0.f, a2 = 0.f, a3 = 0.f;
    for (; i + 3 * stride < PER_B4; i += 4 * stride) {
        float4 v0 = p[i];
        float4 v1 = p[i + stride];
        float4 v2 = p[i + 2 * stride];
        float4 v3 = p[i + 3 * stride];
        a0 += (v0.x + v0.y) + (v0.z + v0.w);
        a1 += (v1.x + v1.y) + (v1.z + v1.w);
        a2 += (v2.x + v2.y) + (v2.z + v2.w);
        a3 += (v3.x + v3.y) + (v3.z + v3.w);
    }
    for (; i < PER_B4; i += stride) {
        float4 v = p[i];
        a0 += (v.x + v.y) + (v.z + v.w);
    }
    float s = (a0 + a1) + (a2 + a3);

    __shared__ float sm[256];
    sm[threadIdx.x] = s;
    __syncthreads();
    for (int o = 128; o > 0; o >>= 1) {
        if (threadIdx.x < o) sm[threadIdx.x] += sm[threadIdx.x + o];
        __syncthreads();
    }
    if (threadIdx.x == 0) d_partial[b * RBLK + blk] = sm[0];
}

// ---------------------------------------------------------------------------
// Kernel B (overlaps reduce): valid-corner bilinear blend (invalid corners
// contribute 0 — no mean dependency). Records w_inv + per-row OOB flag.
// grid = (OUT, NB), threadIdx.x = ox.
// ---------------------------------------------------------------------------
__global__ void bilinear_main_kernel(const float* __restrict__ im,
                                     const float* __restrict__ pos,
                                     const float* __restrict__ szs,
                                     float* __restrict__ out) {
    const int oy = blockIdx.x;
    const int b  = blockIdx.y;
    const int ox = threadIdx.x;
    const bool act = (ox < OUT);

    float w_inv = 0.0f;

    if (act) {
        const float sz    = __ldg(&szs[b]);
        const float half  = (sz + 1.0f) * 0.5f;
        const float xmin  = rintf(__ldg(&pos[2 * b + 0]) - half);
        const float ymin  = rintf(__ldg(&pos[2 * b + 1]) - half);
        const float scale = sz / (float)OUT;
        const float szm1  = sz - 1.0f;

        float sx = fminf(fmaxf(((float)ox + 0.5f) * scale - 0.5f, 0.0f), szm1);
        float lx = floorf(sx);
        float wx = sx - lx;
        float hx = fminf(lx + 1.0f, szm1);

        float sy = fminf(fmaxf(((float)oy + 0.5f) * scale - 0.5f, 0.0f), szm1);
        float ly = floorf(sy);
        float wy = sy - ly;
        float hy = fminf(ly + 1.0f, szm1);

        float y0 = ly + ymin, y1 = hy + ymin;
        float x0 = lx + xmin, x1 = hx + xmin;

        bool vy0 = (y0 >= 0.0f) & (y0 <= (float)(IH - 1));
        bool vy1 = (y1 >= 0.0f) & (y1 <= (float)(IH - 1));
        bool vx0 = (x0 >= 0.0f) & (x0 <= (float)(IW - 1));
        bool vx1 = (x1 >= 0.0f) & (x1 <= (float)(IW - 1));
        int iy0 = (int)fminf(fmaxf(y0, 0.0f), (float)(IH - 1));
        int iy1 = (int)fminf(fmaxf(y1, 0.0f), (float)(IH - 1));
        int ix0 = (int)fminf(fmaxf(x0, 0.0f), (float)(IW - 1));
        int ix1 = (int)fminf(fmaxf(x1, 0.0f), (float)(IW - 1));
        bool v00 = vy0 & vx0, v01 = vy0 & vx1, v10 = vy1 & vx0, v11 = vy1 & vx1;

        const int o00 = iy0 * IW + ix0;
        const int o01 = iy0 * IW + ix1;
        const int o10 = iy1 * IW + ix0;
        const int o11 = iy1 * IW + ix1;

        const float omwx = 1.0f - wx, omwy = 1.0f - wy;
        const float w00 = omwx * omwy, w01 = wx * omwy;
        const float w10 = omwx * wy,  w11 = wx * wy;
        w_inv = (v00 ? 0.0f : w00) + (v01 ? 0.0f : w01) +
                (v10 ? 0.0f : w10) + (v11 ? 0.0f : w11);

        const float* base = im + (size_t)b * PER_B;
        float* orow = out + ((size_t)(b * NC) * OUT + oy) * OUT + ox;

        #pragma unroll
        for (int c = 0; c < NC; c++) {
            const float* pl = base + c * (IH * IW);
            float p00 = v00 ? __ldg(&pl[o00]) : 0.0f;
            float p01 = v01 ? __ldg(&pl[o01]) : 0.0f;
            float p10 = v10 ? __ldg(&pl[o10]) : 0.0f;
            float p11 = v11 ? __ldg(&pl[o11]) : 0.0f;
            float top = p00 * omwx + p01 * wx;
            float bot = p10 * omwx + p11 * wx;
            orow[c * (OUT * OUT)] = top * omwy + bot * wy;
        }
    }

    int any = __syncthreads_or(w_inv > 0.0f ? 1 : 0);
    if (any && act) d_winv[(b * OUT + oy) * OUT + ox] = w_inv;
    if (threadIdx.x == 0) d_rowflag[b * OUT + oy] = any;
}

// ---------------------------------------------------------------------------
// Kernel C (join): finalize batch mean from partials, patch OOB pixels.
// grid = (OUT, NB); early-exits rows with no OOB corners.
// ---------------------------------------------------------------------------
__global__ void patch_kernel(float* __restrict__ out) {
    const int oy = blockIdx.x;
    const int b  = blockIdx.y;

    if (d_rowflag[b * OUT + oy] == 0) return;

    __shared__ float s_mean;
    if (threadIdx.x < 32) {
        const int l = threadIdx.x;
        const float* pp = &d_partial[b * RBLK];
        float s = pp[l] + pp[l + 32];
        if (l < RBLK - 64) s += pp[l + 64];
        #pragma unroll
        for (int o = 16; o > 0; o >>= 1) s += __shfl_down_sync(0xffffffffu, s, o);
        if (l == 0) s_mean = s * (1.0f / (float)PER_B);
    }
    __syncthreads();

    const int ox = threadIdx.x;
    if (ox >= OUT) return;

    float w_inv = d_winv[(b * OUT + oy) * OUT + ox];
    if (w_inv > 0.0f) {
        float add = w_inv * s_mean;
        float* orow = out + ((size_t)(b * NC) * OUT + oy) * OUT + ox;
        #pragma unroll
        for (int c = 0; c < NC; c++) orow[c * (OUT * OUT)] += add;
    }
}

// ---------------------------------------------------------------------------
extern "C" void kernel_launch(void* const* d_in, const int* in_sizes, int n_in,
                              void* d_out, int out_size) {
    const float* im  = (const float*)d_in[0];
    const float* pos = (const float*)d_in[1];
    const float* szs = (const float*)d_in[2];
    float* out = (float*)d_out;

    int prio_lo, prio_hi;
    cudaDeviceGetStreamPriorityRange(&prio_lo, &prio_hi);

    cudaStream_t s_hi;
    cudaEvent_t e_fork, e_join;
    cudaStreamCreateWithPriority(&s_hi, cudaStreamNonBlocking, prio_hi);
    cudaEventCreateWithFlags(&e_fork, cudaEventDisableTiming);
    cudaEventCreateWithFlags(&e_join, cudaEventDisableTiming);

    // fork: reduce runs on high-priority side stream
    cudaEventRecord(e_fork, 0);
    cudaStreamWaitEvent(s_hi, e_fork, 0);
    reduce_kernel<<<dim3(RBLK, NB), 256, 0, s_hi>>>(im);
    cudaEventRecord(e_join, s_hi);

    // main stream: mean-independent bilinear, overlapping the reduce
    bilinear_main_kernel<<<dim3(OUT, NB), 256>>>(im, pos, szs, out);

    // join: patch OOB pixels with mean contribution
    cudaStreamWaitEvent(0, e_join, 0);
    patch_kernel<<<dim3(OUT, NB), 256>>>(out);
}

// round 7
// speedup vs baseline: 1.1029x; 1.1029x over previous
#include <cuda_runtime.h>

#define NB 16
#define NC 3
#define IH 720
#define IW 1280
#define OUT 255
#define PER_B (NC*IH*IW)          /* 2764800 floats per batch image */
#define PER_B4 (PER_B/4)          /* 691200 float4 per batch image */
#define RBLK 74                   /* reduction blocks per batch */
#define NRED (RBLK*NB)            /* 1184 reduce blocks */

__device__ float d_partial[NB * RBLK];
__device__ float d_mean[NB];
__device__ unsigned int d_count = 0;   /* wrapping block counter (replay-safe) */
__device__ volatile int d_flag = 0;    /* release flag: means are ready */

// ---------------------------------------------------------------------------
// Kernel A: per-batch partial sums; last block finalizes all means + sets flag.
// grid = (RBLK, NB) = 1184 blocks, block = 256.
// ---------------------------------------------------------------------------
__global__ void reduce_kernel(const float* __restrict__ im) {
    const int b   = blockIdx.y;
    const int blk = blockIdx.x;
    const float4* __restrict__ p = (const float4*)(im + (size_t)b * PER_B);

    const int stride = RBLK * 256;            /* 18944 */
    int i = blk * 256 + threadIdx.x;

    float a0 = 0.f, a1 = 0.f, a2 = 0.f, a3 = 0.f;
    for (; i + 3 * stride < PER_B4; i += 4 * stride) {
        float4 v0 = p[i];
        float4 v1 = p[i + stride];
        float4 v2 = p[i + 2 * stride];
        float4 v3 = p[i + 3 * stride];
        a0 += (v0.x + v0.y) + (v0.z + v0.w);
        a1 += (v1.x + v1.y) + (v1.z + v1.w);
        a2 += (v2.x + v2.y) + (v2.z + v2.w);
        a3 += (v3.x + v3.y) + (v3.z + v3.w);
    }
    for (; i < PER_B4; i += stride) {
        float4 v = p[i];
        a0 += (v.x + v.y) + (v.z + v.w);
    }
    float s = (a0 + a1) + (a2 + a3);

    __shared__ float sm[256];
    sm[threadIdx.x] = s;
    __syncthreads();
    for (int o = 128; o > 0; o >>= 1) {
        if (threadIdx.x < o) sm[threadIdx.x] += sm[threadIdx.x + o];
        __syncthreads();
    }
    if (threadIdx.x == 0) d_partial[b * RBLK + blk] = sm[0];

    /* last-block-done detection (wrapping -> graph-replay safe) */
    __shared__ int s_last;
    if (threadIdx.x == 0) {
        __threadfence();                               /* partial visible in L2 */
        unsigned int old = atomicInc(&d_count, NRED - 1);
        s_last = (old == NRED - 1);
    }
    __syncthreads();

    if (s_last) {
        /* finalize all 16 means: warp w handles batches 2w, 2w+1 */
        const int w = threadIdx.x >> 5;
        const int l = threadIdx.x & 31;
        #pragma unroll
        for (int k = 0; k < 2; k++) {
            const int bb = w * 2 + k;
            const float* pp = &d_partial[bb * RBLK];
            float s2 = __ldcg(&pp[l]) + __ldcg(&pp[l + 32]);
            if (l < RBLK - 64) s2 += __ldcg(&pp[l + 64]);
            #pragma unroll
            for (int o = 16; o > 0; o >>= 1) s2 += __shfl_down_sync(0xffffffffu, s2, o);
            if (l == 0) d_mean[bb] = s2 * (1.0f / (float)PER_B);
        }
        __syncthreads();
        if (threadIdx.x == 0) {
            __threadfence();                           /* means visible before flag */
            atomicExch((int*)&d_flag, 1);
        }
    }
}

// ---------------------------------------------------------------------------
// Kernel B (concurrent): bilinear. Valid blend held in registers; blocks with
// any OOB corner wait on the flag, add w_inv * mean, then store once.
// grid = (OUT, NB), threadIdx.x = ox.
// ---------------------------------------------------------------------------
__global__ void bilinear_kernel(const float* __restrict__ im,
                                const float* __restrict__ pos,
                                const float* __restrict__ szs,
                                float* __restrict__ out) {
    const int oy = blockIdx.x;
    const int b  = blockIdx.y;
    const int ox = threadIdx.x;
    const bool act = (ox < OUT);

    float w_inv = 0.0f;
    float r0 = 0.f, r1 = 0.f, r2 = 0.f;

    if (act) {
        const float sz    = __ldg(&szs[b]);
        const float half  = (sz + 1.0f) * 0.5f;
        const float xmin  = rintf(__ldg(&pos[2 * b + 0]) - half);  /* jnp.round */
        const float ymin  = rintf(__ldg(&pos[2 * b + 1]) - half);
        const float scale = sz / (float)OUT;
        const float szm1  = sz - 1.0f;

        float sx = fminf(fmaxf(((float)ox + 0.5f) * scale - 0.5f, 0.0f), szm1);
        float lx = floorf(sx);
        float wx = sx - lx;
        float hx = fminf(lx + 1.0f, szm1);

        float sy = fminf(fmaxf(((float)oy + 0.5f) * scale - 0.5f, 0.0f), szm1);
        float ly = floorf(sy);
        float wy = sy - ly;
        float hy = fminf(ly + 1.0f, szm1);

        float y0 = ly + ymin, y1 = hy + ymin;
        float x0 = lx + xmin, x1 = hx + xmin;

        bool vy0 = (y0 >= 0.0f) & (y0 <= (float)(IH - 1));
        bool vy1 = (y1 >= 0.0f) & (y1 <= (float)(IH - 1));
        bool vx0 = (x0 >= 0.0f) & (x0 <= (float)(IW - 1));
        bool vx1 = (x1 >= 0.0f) & (x1 <= (float)(IW - 1));
        int iy0 = (int)fminf(fmaxf(y0, 0.0f), (float)(IH - 1));
        int iy1 = (int)fminf(fmaxf(y1, 0.0f), (float)(IH - 1));
        int ix0 = (int)fminf(fmaxf(x0, 0.0f), (float)(IW - 1));
        int ix1 = (int)fminf(fmaxf(x1, 0.0f), (float)(IW - 1));
        bool v00 = vy0 & vx0, v01 = vy0 & vx1, v10 = vy1 & vx0, v11 = vy1 & vx1;

        const int o00 = iy0 * IW + ix0;
        const int o01 = iy0 * IW + ix1;
        const int o10 = iy1 * IW + ix0;
        const int o11 = iy1 * IW + ix1;

        const float omwx = 1.0f - wx, omwy = 1.0f - wy;
        const float w00 = omwx * omwy, w01 = wx * omwy;
        const float w10 = omwx * wy,  w11 = wx * wy;
        w_inv = (v00 ? 0.0f : w00) + (v01 ? 0.0f : w01) +
                (v10 ? 0.0f : w10) + (v11 ? 0.0f : w11);

        const float* base = im + (size_t)b * PER_B;
        {
            const float* pl = base;
            float p00 = v00 ? __ldg(&pl[o00]) : 0.0f;
            float p01 = v01 ? __ldg(&pl[o01]) : 0.0f;
            float p10 = v10 ? __ldg(&pl[o10]) : 0.0f;
            float p11 = v11 ? __ldg(&pl[o11]) : 0.0f;
            r0 = (p00 * omwx + p01 * wx) * omwy + (p10 * omwx + p11 * wx) * wy;
        }
        {
            const float* pl = base + IH * IW;
            float p00 = v00 ? __ldg(&pl[o00]) : 0.0f;
            float p01 = v01 ? __ldg(&pl[o01]) : 0.0f;
            float p10 = v10 ? __ldg(&pl[o10]) : 0.0f;
            float p11 = v11 ? __ldg(&pl[o11]) : 0.0f;
            r1 = (p00 * omwx + p01 * wx) * omwy + (p10 * omwx + p11 * wx) * wy;
        }
        {
            const float* pl = base + 2 * (IH * IW);
            float p00 = v00 ? __ldg(&pl[o00]) : 0.0f;
            float p01 = v01 ? __ldg(&pl[o01]) : 0.0f;
            float p10 = v10 ? __ldg(&pl[o10]) : 0.0f;
            float p11 = v11 ? __ldg(&pl[o11]) : 0.0f;
            r2 = (p00 * omwx + p01 * wx) * omwy + (p10 * omwx + p11 * wx) * wy;
        }
    }

    /* block-level join: only OOB-touching blocks wait for the mean */
    int need = __syncthreads_or((w_inv > 0.0f) ? 1 : 0);
    if (need) {
        if (threadIdx.x == 0) {
            while (d_flag == 0) __nanosleep(200);
        }
        __syncthreads();
        if (act && w_inv > 0.0f) {
            float add = w_inv * __ldcg(&d_mean[b]);
            r0 += add; r1 += add; r2 += add;
        }
    }

    if (act) {
        float* orow = out + ((size_t)(b * NC) * OUT + oy) * OUT + ox;
        orow[0]         = r0;
        orow[OUT * OUT]     = r1;
        orow[2 * OUT * OUT] = r2;
    }
}

// ---------------------------------------------------------------------------
extern "C" void kernel_launch(void* const* d_in, const int* in_sizes, int n_in,
                              void* d_out, int out_size) {
    const float* im  = (const float*)d_in[0];
    const float* pos = (const float*)d_in[1];
    const float* szs = (const float*)d_in[2];
    float* out = (float*)d_out;

    int prio_lo, prio_hi;
    cudaDeviceGetStreamPriorityRange(&prio_lo, &prio_hi);

    cudaStream_t s_hi;
    cudaEvent_t e_fork, e_join;
    cudaStreamCreateWithPriority(&s_hi, cudaStreamNonBlocking, prio_hi);
    cudaEventCreateWithFlags(&e_fork, cudaEventDisableTiming);
    cudaEventCreateWithFlags(&e_join, cudaEventDisableTiming);

    /* fork: reduce on high-priority side stream, bilinear on main stream */
    cudaEventRecord(e_fork, 0);
    cudaStreamWaitEvent(s_hi, e_fork, 0);
    reduce_kernel<<<dim3(RBLK, NB), 256, 0, s_hi>>>(im);
    cudaEventRecord(e_join, s_hi);

    bilinear_kernel<<<dim3(OUT, NB), 256>>>(im, pos, szs, out);

    /* join so the graph's end states both branches complete */
    cudaStreamWaitEvent(0, e_join, 0);
}